// round 9
// baseline (speedup 1.0000x reference)
#include <cuda_runtime.h>
#include <cstdint>

typedef unsigned long long u64;

#define NPTSALL    16384     // BATCH * N_PTS
#define NFACES     10000
#define NPAIRS     5000      // NFACES / 2
#define NOCT       8
#define OCT_PAIRS  625       // NPAIRS / NOCT
#define OCT_FACES  1250
#define NSUB       25
#define SUB_PAIRS  25        // OCT_PAIRS / NSUB
#define SSCALE     10.0f

// Scratch (static __device__ arrays; no allocation)
__device__ float d_A[NPAIRS * 4];          // (cx0, cx1, cy0, cy1) per center pair
__device__ float d_B[NPAIRS * 4];          // (cz0, cz1, c2_0, c2_1) per center pair
__device__ float  d_qval[NOCT * NPTSALL];  // per-octant min score per point
__device__ int    d_qsub[NOCT * NPTSALL];  // winning subtile base pair index

// ---------------- packed fp32x2 helpers ----------------
__device__ __forceinline__ u64 fma2(u64 a, u64 b, u64 c) {
    u64 d;
    asm("fma.rn.f32x2 %0, %1, %2, %3;" : "=l"(d) : "l"(a), "l"(b), "l"(c));
    return d;
}
__device__ __forceinline__ u64 pk2(float lo, float hi) {
    u64 v; asm("mov.b64 %0, {%1, %2};" : "=l"(v) : "f"(lo), "f"(hi)); return v;
}
__device__ __forceinline__ void upk2(u64 v, float& lo, float& hi) {
    asm("mov.b64 {%0, %1}, %2;" : "=f"(lo), "=f"(hi) : "l"(v));
}

// ---------------- 1+2a) fused: compute octant centers in-block, then min scan ----------------
// Every block computes its octant's 625 center-pairs from V/F into smem using
// EXACTLY the expressions the old pack kernel used (identical inputs + identical
// ops across blocks => identical bits). x-block 0 of each octant also writes the
// pairs to global d_A/d_B for the solve kernel's rescan (kernel-boundary ordered).
// Scan: score_f = |c_f|^2 - 2 q . c_f (|q|^2 dropped: argmin-invariant); 2 points
// per thread; min VALUE per 25-pair subtile; strict < ascending => first-index ties.
__global__ void __launch_bounds__(128) knnA_kernel(
    const float* __restrict__ verts,
    const float* __restrict__ V,
    const int*   __restrict__ F)
{
    __shared__ alignas(16) float sAf[OCT_PAIRS * 4];   // 10 KB
    __shared__ alignas(16) float sBf[OCT_PAIRS * 4];   // 10 KB
    int tid = threadIdx.x;
    int oct = blockIdx.y;
    int obase = oct * OCT_PAIRS;
    int fbase = oct * OCT_FACES;

    // ---- compute centers for this octant (same exprs as the old pack kernel) ----
    for (int fl = tid; fl < OCT_FACES; fl += 128) {
        int f = fbase + fl;
        int i0 = F[3*f+0], i1 = F[3*f+1], i2 = F[3*f+2];
        float x = (V[3*i0+0] + V[3*i1+0] + V[3*i2+0]) / 3.0f;
        float y = (V[3*i0+1] + V[3*i1+1] + V[3*i2+1]) / 3.0f;
        float z = (V[3*i0+2] + V[3*i1+2] + V[3*i2+2]) / 3.0f;
        float c2 = x*x + y*y + z*z;
        int p = fl >> 1, h = fl & 1;
        sAf[4*p + h]     = x;
        sAf[4*p + 2 + h] = y;
        sBf[4*p + h]     = z;
        sBf[4*p + 2 + h] = c2;
        if (blockIdx.x == 0) {   // one x-block per octant materializes globals for rescan
            int gp = obase + p;
            d_A[4*gp + h]     = x;
            d_A[4*gp + 2 + h] = y;
            d_B[4*gp + h]     = z;
            d_B[4*gp + 2 + h] = c2;
        }
    }
    __syncthreads();

    const ulonglong2* sA = (const ulonglong2*)sAf;
    const ulonglong2* sB = (const ulonglong2*)sBf;

    int ptA = blockIdx.x * 256 + tid;
    int ptB = ptA + 128;
    float qxA = verts[3*ptA+0], qyA = verts[3*ptA+1], qzA = verts[3*ptA+2];
    float qxB = verts[3*ptB+0], qyB = verts[3*ptB+1], qzB = verts[3*ptB+2];
    u64 qmxA = pk2(-2.0f*qxA, -2.0f*qxA);
    u64 qmyA = pk2(-2.0f*qyA, -2.0f*qyA);
    u64 qmzA = pk2(-2.0f*qzA, -2.0f*qzA);
    u64 qmxB = pk2(-2.0f*qxB, -2.0f*qxB);
    u64 qmyB = pk2(-2.0f*qyB, -2.0f*qyB);
    u64 qmzB = pk2(-2.0f*qzB, -2.0f*qzB);

    const float INF = __int_as_float(0x7f800000);
    float bestA = INF, bestB = INF;
    int subA = 0, subB = 0;

#pragma unroll 1
    for (int s = 0; s < NSUB; ++s) {
        int b = s * SUB_PAIRS;
        float a0 = INF, a1 = INF, b0 = INF, b1 = INF;
#pragma unroll 5
        for (int p = 0; p < SUB_PAIRS; ++p) {
            ulonglong2 A = sA[b + p];
            ulonglong2 B = sB[b + p];
            u64 zA = fma2(B.x, qmzA, B.y);
            u64 zB = fma2(B.x, qmzB, B.y);
            u64 scA = fma2(A.x, qmxA, fma2(A.y, qmyA, zA));
            u64 scB = fma2(A.x, qmxB, fma2(A.y, qmyB, zB));
            float lA, hA, lB, hB;
            upk2(scA, lA, hA); upk2(scB, lB, hB);
            a0 = fminf(a0, lA); a1 = fminf(a1, hA);
            b0 = fminf(b0, lB); b1 = fminf(b1, hB);
        }
        float smA = fminf(a0, a1);
        float smB = fminf(b0, b1);
        if (smA < bestA) { bestA = smA; subA = b; }   // strict <: earliest subtile wins
        if (smB < bestB) { bestB = smB; subB = b; }
    }
    d_qval[oct * NPTSALL + ptA] = bestA;
    d_qsub[oct * NPTSALL + ptA] = obase + subA;
    d_qval[oct * NPTSALL + ptB] = bestB;
    d_qsub[oct * NPTSALL + ptB] = obase + subB;
}

// ---------------- 2b + 3) combine/rescan + 4 x 50 Adam solve ----------------
// R8 form VERBATIM (validated at rel_err 8.026817e-4).
__global__ void __launch_bounds__(128) solve_kernel(
    const float* __restrict__ verts,
    const float* __restrict__ MV,
    const float* __restrict__ MN,
    const int*   __restrict__ MF,
    float* __restrict__ out)
{
    int i = blockIdx.x * 128 + threadIdx.x;

    float qx = verts[3*i+0], qy = verts[3*i+1], qz = verts[3*i+2];

    // ---- combine octant mins (strict <, ascending => first-index ties) ----
    float best = d_qval[i]; int qi = 0;
#pragma unroll
    for (int q = 1; q < NOCT; ++q) {
        float v = d_qval[q * NPTSALL + i];
        if (v < best) { best = v; qi = q; }
    }
    int base = d_qsub[qi * NPTSALL + i];

    // ---- rescan winning 25-pair subtile, first bitwise-equal index ----
    u64 qmx = pk2(-2.0f*qx, -2.0f*qx);
    u64 qmy = pk2(-2.0f*qy, -2.0f*qy);
    u64 qmz = pk2(-2.0f*qz, -2.0f*qz);
    const ulonglong2* gA = (const ulonglong2*)d_A;
    const ulonglong2* gB = (const ulonglong2*)d_B;
    int found = 0x7fffffff;
#pragma unroll 5
    for (int j = 0; j < SUB_PAIRS; ++j) {
        ulonglong2 a = gA[base + j];
        ulonglong2 b = gB[base + j];
        u64 sc = fma2(a.x, qmx, fma2(a.y, qmy, fma2(b.x, qmz, b.y)));
        float lo, hi; upk2(sc, lo, hi);
        if (lo == best) found = min(found, 2*(base + j));
        if (hi == best) found = min(found, 2*(base + j) + 1);
    }
    int fid = (found == 0x7fffffff) ? 0 : found;   // guaranteed found; OOB guard

    // ---- Adam solve (numerics identical to R2/R4/R8) ----
    int i0 = MF[3*fid+0], i1 = MF[3*fid+1], i2 = MF[3*fid+2];

    float V0x = MV[3*i0+0], V0y = MV[3*i0+1], V0z = MV[3*i0+2];
    float V1x = MV[3*i1+0], V1y = MV[3*i1+1], V1z = MV[3*i1+2];
    float V2x = MV[3*i2+0], V2y = MV[3*i2+1], V2z = MV[3*i2+2];
    float N0x = MN[3*i0+0], N0y = MN[3*i0+1], N0z = MN[3*i0+2];
    float N1x = MN[3*i1+0], N1y = MN[3*i1+1], N1z = MN[3*i1+2];
    float N2x = MN[3*i2+0], N2y = MN[3*i2+1], N2z = MN[3*i2+2];

    float tgx = SSCALE*qx, tgy = SSCALE*qy, tgz = SSCALE*qz;

    float dVux = V0x - V2x, dVuy = V0y - V2y, dVuz = V0z - V2z;
    float dVvx = V1x - V2x, dVvy = V1y - V2y, dVvz = V1z - V2z;
    float dNux = N0x - N2x, dNuy = N0y - N2y, dNuz = N0z - N2z;
    float dNvx = N1x - N2x, dNvy = N1y - N2y, dNvz = N1z - N2z;

    const float B1 = 0.9f, B2 = 0.999f, LR = 0.01f, EPSA = 1e-8f;
    const float OB1 = 1.0f - 0.9f;
    const float OB2 = 1.0f - 0.999f;
    const float K   = (2.0f / 49152.0f) * SSCALE;  // 2/(3M) * S

    float vwu = 1.0f/3.0f, vwv = 1.0f/3.0f;

#pragma unroll 1
    for (int outer = 0; outer < 4; ++outer) {
        float w0 = 1.0f - vwu - vwv;
        float Px0 = fmaf(vwu, V0x, fmaf(vwv, V1x, w0 * V2x));
        float Py0 = fmaf(vwu, V0y, fmaf(vwv, V1y, w0 * V2y));
        float Pz0 = fmaf(vwu, V0z, fmaf(vwv, V1z, w0 * V2z));
        float ex = Px0 - qx, ey = Py0 - qy, ez = Pz0 - qz;
        float dd = sqrtf(ex*ex + ey*ey + ez*ez);

        float du = 0.0f, dv = 0.0f;
        float mu = 0.0f, mv = 0.0f, md = 0.0f;
        float vu = 0.0f, vvv = 0.0f, vd = 0.0f;
        float b1t = 1.0f, b2t = 1.0f;

#pragma unroll 1
        for (int t = 0; t < 50; ++t) {
            b1t *= B1; b2t *= B2;
            float u = vwu + du, v = vwv + dv;
            float w = 1.0f - u - v;

            float Px = fmaf(u, V0x, fmaf(v, V1x, w * V2x));
            float Py = fmaf(u, V0y, fmaf(v, V1y, w * V2y));
            float Pz = fmaf(u, V0z, fmaf(v, V1z, w * V2z));
            float Nx = fmaf(u, N0x, fmaf(v, N1x, w * N2x));
            float Ny = fmaf(u, N0y, fmaf(v, N1y, w * N2y));
            float Nz = fmaf(u, N0z, fmaf(v, N1z, w * N2z));

            float nn = fmaf(Nx, Nx, fmaf(Ny, Ny, Nz * Nz));
            float l  = sqrtf(nn);
            float rl = __fdividef(1.0f, fmaxf(l, 1e-12f));
            float nx = Nx * rl, ny = Ny * rl, nz = Nz * rl;

            float sd = SSCALE * dd;
            float rx = fmaf(SSCALE, Px, fmaf(sd, nx, -tgx));
            float ry = fmaf(SSCALE, Py, fmaf(sd, ny, -tgy));
            float rz = fmaf(SSCALE, Pz, fmaf(sd, nz, -tgz));

            float rn  = fmaf(rx, nx,   fmaf(ry, ny,   rz * nz));
            float rvu = fmaf(rx, dVux, fmaf(ry, dVuy, rz * dVuz));
            float rvv = fmaf(rx, dVvx, fmaf(ry, dVvy, rz * dVvz));
            float rnu = fmaf(rx, dNux, fmaf(ry, dNuy, rz * dNuz));
            float rnv = fmaf(rx, dNvx, fmaf(ry, dNvy, rz * dNvz));
            float ndu = fmaf(nx, dNux, fmaf(ny, dNuy, nz * dNuz));
            float ndv = fmaf(nx, dNvx, fmaf(ny, dNvy, nz * dNvz));

            float drl = dd * rl;
            float gu = K * fmaf(drl, fmaf(-ndu, rn, rnu), rvu);
            float gv = K * fmaf(drl, fmaf(-ndv, rn, rnv), rvv);
            float gd = K * rn;

            float ic1 = __fdividef(1.0f, 1.0f - b1t);
            float ic2 = __fdividef(1.0f, 1.0f - b2t);

            mu = fmaf(B1, mu, OB1 * gu);
            vu = fmaf(B2, vu, OB2 * gu * gu);
            du = fmaf(-LR, __fdividef(mu * ic1, sqrtf(vu * ic2) + EPSA), du);

            mv = fmaf(B1, mv, OB1 * gv);
            vvv = fmaf(B2, vvv, OB2 * gv * gv);
            dv = fmaf(-LR, __fdividef(mv * ic1, sqrtf(vvv * ic2) + EPSA), dv);

            md = fmaf(B1, md, OB1 * gd);
            vd = fmaf(B2, vd, OB2 * gd * gd);
            dd = fmaf(-LR, __fdividef(md * ic1, sqrtf(vd * ic2) + EPSA), dd);
        }
        vwu += du; vwv += dv;
    }

    // Outputs, flattened tuple as float32: fidx | vw | outlier_mask
    out[i] = (float)fid;
    out[NPTSALL + 2*i + 0] = vwu;
    out[NPTSALL + 2*i + 1] = vwv;
    out[3*NPTSALL + i] = 0.0f;
}

extern "C" void kernel_launch(void* const* d_in, const int* in_sizes, int n_in,
                              void* d_out, int out_size) {
    const float* verts  = (const float*)d_in[0];
    const float* mesh_V = (const float*)d_in[1];
    const float* mesh_N = (const float*)d_in[2];
    const int*   mesh_F = (const int*)d_in[3];
    float* out = (float*)d_out;

    dim3 gridA(NPTSALL / 256, NOCT);
    knnA_kernel<<<gridA, 128>>>(verts, mesh_V, mesh_F);
    solve_kernel<<<NPTSALL / 128, 128>>>(verts, mesh_V, mesh_N, mesh_F, out);
}

// round 10
// speedup vs baseline: 1.2985x; 1.2985x over previous
#include <cuda_runtime.h>
#include <cstdint>

typedef unsigned long long u64;

#define NPTSALL    16384     // BATCH * N_PTS
#define NFACES     10000
#define NPAIRS     5000      // NFACES / 2
#define NOCT       8
#define OCT_PAIRS  625       // NPAIRS / NOCT
#define NSUB       25
#define SUB_PAIRS  25        // OCT_PAIRS / NSUB
#define SSCALE     10.0f

// Scratch (static __device__ arrays; no allocation)
__device__ float4 d_A[NPAIRS];             // (cx0, cx1, cy0, cy1) per center pair
__device__ float4 d_B[NPAIRS];             // (cz0, cz1, c2_0, c2_1) per center pair
__device__ float  d_qval[NOCT * NPTSALL];  // per-octant min score per point
__device__ int    d_qsub[NOCT * NPTSALL];  // winning subtile base pair index

// ---------------- packed fp32x2 helpers ----------------
__device__ __forceinline__ u64 fma2(u64 a, u64 b, u64 c) {
    u64 d;
    asm("fma.rn.f32x2 %0, %1, %2, %3;" : "=l"(d) : "l"(a), "l"(b), "l"(c));
    return d;
}
__device__ __forceinline__ u64 mul2(u64 a, u64 b) {
    u64 d;
    asm("mul.rn.f32x2 %0, %1, %2;" : "=l"(d) : "l"(a), "l"(b));
    return d;
}
__device__ __forceinline__ u64 add2(u64 a, u64 b) {
    u64 d;
    asm("add.rn.f32x2 %0, %1, %2;" : "=l"(d) : "l"(a), "l"(b));
    return d;
}
__device__ __forceinline__ u64 pk2(float lo, float hi) {
    u64 v; asm("mov.b64 %0, {%1, %2};" : "=l"(v) : "f"(lo), "f"(hi)); return v;
}
__device__ __forceinline__ void upk2(u64 v, float& lo, float& hi) {
    asm("mov.b64 {%0, %1}, %2;" : "=f"(lo), "=f"(hi) : "l"(v));
}

// ---------------- 1) centers + |c|^2 (one thread per face) ----------------
__global__ void pack_centers_kernel(const float* __restrict__ V, const int* __restrict__ F) {
    int f = blockIdx.x * blockDim.x + threadIdx.x;
    if (f >= NFACES) return;
    int i0 = F[3*f+0], i1 = F[3*f+1], i2 = F[3*f+2];
    float x = (V[3*i0+0] + V[3*i1+0] + V[3*i2+0]) / 3.0f;
    float y = (V[3*i0+1] + V[3*i1+1] + V[3*i2+1]) / 3.0f;
    float z = (V[3*i0+2] + V[3*i1+2] + V[3*i2+2]) / 3.0f;
    float c2 = x*x + y*y + z*z;
    int p = f >> 1, h = f & 1;
    float* A = (float*)d_A;
    float* B = (float*)d_B;
    A[4*p + h]     = x;
    A[4*p + 2 + h] = y;
    B[4*p + h]     = z;
    B[4*p + 2 + h] = c2;
}

// ---------------- 2a) per-octant min scan, 2 points per thread ----------------
// R8 form VERBATIM. score_f = |c_f|^2 - 2 q.c_f; min VALUE per 25-pair subtile;
// strict < ascending => first-index ties.
__global__ void __launch_bounds__(128) knnA_kernel(const float* __restrict__ verts) {
    __shared__ ulonglong2 sA[OCT_PAIRS];   // 10 KB
    __shared__ ulonglong2 sB[OCT_PAIRS];   // 10 KB
    int tid = threadIdx.x;
    int oct = blockIdx.y;
    int obase = oct * OCT_PAIRS;

    const ulonglong2* gA = (const ulonglong2*)d_A;
    const ulonglong2* gB = (const ulonglong2*)d_B;
    for (int i = tid; i < OCT_PAIRS; i += 128) { sA[i] = gA[obase + i]; sB[i] = gB[obase + i]; }
    __syncthreads();

    int ptA = blockIdx.x * 256 + tid;
    int ptB = ptA + 128;
    float qxA = verts[3*ptA+0], qyA = verts[3*ptA+1], qzA = verts[3*ptA+2];
    float qxB = verts[3*ptB+0], qyB = verts[3*ptB+1], qzB = verts[3*ptB+2];
    u64 qmxA = pk2(-2.0f*qxA, -2.0f*qxA);
    u64 qmyA = pk2(-2.0f*qyA, -2.0f*qyA);
    u64 qmzA = pk2(-2.0f*qzA, -2.0f*qzA);
    u64 qmxB = pk2(-2.0f*qxB, -2.0f*qxB);
    u64 qmyB = pk2(-2.0f*qyB, -2.0f*qyB);
    u64 qmzB = pk2(-2.0f*qzB, -2.0f*qzB);

    const float INF = __int_as_float(0x7f800000);
    float bestA = INF, bestB = INF;
    int subA = 0, subB = 0;

#pragma unroll 1
    for (int s = 0; s < NSUB; ++s) {
        int b = s * SUB_PAIRS;
        float a0 = INF, a1 = INF, b0 = INF, b1 = INF;
#pragma unroll 5
        for (int p = 0; p < SUB_PAIRS; ++p) {
            ulonglong2 A = sA[b + p];
            ulonglong2 B = sB[b + p];
            u64 zA = fma2(B.x, qmzA, B.y);
            u64 zB = fma2(B.x, qmzB, B.y);
            u64 scA = fma2(A.x, qmxA, fma2(A.y, qmyA, zA));
            u64 scB = fma2(A.x, qmxB, fma2(A.y, qmyB, zB));
            float lA, hA, lB, hB;
            upk2(scA, lA, hA); upk2(scB, lB, hB);
            a0 = fminf(a0, lA); a1 = fminf(a1, hA);
            b0 = fminf(b0, lB); b1 = fminf(b1, hB);
        }
        float smA = fminf(a0, a1);
        float smB = fminf(b0, b1);
        if (smA < bestA) { bestA = smA; subA = b; }   // strict <: earliest subtile wins
        if (smB < bestB) { bestB = smB; subB = b; }
    }
    d_qval[oct * NPTSALL + ptA] = bestA;
    d_qsub[oct * NPTSALL + ptA] = obase + subA;
    d_qval[oct * NPTSALL + ptB] = bestB;
    d_qsub[oct * NPTSALL + ptB] = obase + subB;
}

// ---------------- 2b + 3) combine/rescan + 4 x 50 Adam solve, u/v lane-packed ----------------
// One point per thread (512 warps). The u-pipeline and v-pipeline of each Adam
// iteration are packed into f32x2 lanes (lo=u, hi=v). Every lane computes the
// EXACT original fp32 op sequence (packed fma/mul/add are per-lane IEEE ops;
// operand negation done via exact *-1.0f before the fma; (OB2*g)*g order kept).
// Scalar parts (w, Pz, Nz, nn, sqrt/div MUFU, rn, dd-branch) unchanged bits.
__global__ void __launch_bounds__(128) solve_kernel(
    const float* __restrict__ verts,
    const float* __restrict__ MV,
    const float* __restrict__ MN,
    const int*   __restrict__ MF,
    float* __restrict__ out)
{
    int i = blockIdx.x * 128 + threadIdx.x;

    float qx = verts[3*i+0], qy = verts[3*i+1], qz = verts[3*i+2];

    // ---- combine octant mins (strict <, ascending => first-index ties) ----
    float best = d_qval[i]; int qi = 0;
#pragma unroll
    for (int q = 1; q < NOCT; ++q) {
        float v = d_qval[q * NPTSALL + i];
        if (v < best) { best = v; qi = q; }
    }
    int base = d_qsub[qi * NPTSALL + i];

    // ---- rescan winning 25-pair subtile, first bitwise-equal index ----
    u64 qmx = pk2(-2.0f*qx, -2.0f*qx);
    u64 qmy = pk2(-2.0f*qy, -2.0f*qy);
    u64 qmz = pk2(-2.0f*qz, -2.0f*qz);
    const ulonglong2* gA = (const ulonglong2*)d_A;
    const ulonglong2* gB = (const ulonglong2*)d_B;
    int found = 0x7fffffff;
#pragma unroll 5
    for (int j = 0; j < SUB_PAIRS; ++j) {
        ulonglong2 a = gA[base + j];
        ulonglong2 b = gB[base + j];
        u64 sc = fma2(a.x, qmx, fma2(a.y, qmy, fma2(b.x, qmz, b.y)));
        float lo, hi; upk2(sc, lo, hi);
        if (lo == best) found = min(found, 2*(base + j));
        if (hi == best) found = min(found, 2*(base + j) + 1);
    }
    int fid = (found == 0x7fffffff) ? 0 : found;   // guaranteed found; OOB guard

    // ---- geometry prologue ----
    int i0 = MF[3*fid+0], i1 = MF[3*fid+1], i2 = MF[3*fid+2];

    float V0x = MV[3*i0+0], V0y = MV[3*i0+1], V0z = MV[3*i0+2];
    float V1x = MV[3*i1+0], V1y = MV[3*i1+1], V1z = MV[3*i1+2];
    float V2x = MV[3*i2+0], V2y = MV[3*i2+1], V2z = MV[3*i2+2];
    float N0x = MN[3*i0+0], N0y = MN[3*i0+1], N0z = MN[3*i0+2];
    float N1x = MN[3*i1+0], N1y = MN[3*i1+1], N1z = MN[3*i1+2];
    float N2x = MN[3*i2+0], N2y = MN[3*i2+1], N2z = MN[3*i2+2];

    float tgx = SSCALE*qx, tgy = SSCALE*qy, tgz = SSCALE*qz;

    float dVux = V0x - V2x, dVuy = V0y - V2y, dVuz = V0z - V2z;
    float dVvx = V1x - V2x, dVvy = V1y - V2y, dVvz = V1z - V2z;
    float dNux = N0x - N2x, dNuy = N0y - N2y, dNuz = N0z - N2z;
    float dNvx = N1x - N2x, dNvy = N1y - N2y, dNvz = N1z - N2z;

    const float B1 = 0.9f, B2 = 0.999f, LR = 0.01f, EPSA = 1e-8f;
    const float OB1 = 1.0f - 0.9f;
    const float OB2 = 1.0f - 0.999f;
    const float K   = (2.0f / 49152.0f) * SSCALE;  // 2/(3M) * S

    // packed loop-invariant data: lo lane = u-pipeline, hi lane = v-pipeline
    u64 dVuv_x = pk2(dVux, dVvx), dVuv_y = pk2(dVuy, dVvy), dVuv_z = pk2(dVuz, dVvz);
    u64 dNuv_x = pk2(dNux, dNvx), dNuv_y = pk2(dNuy, dNvy), dNuv_z = pk2(dNuz, dNvz);
    // packed (x,y) component pairs for the interpolation
    u64 V0xy = pk2(V0x, V0y), V1xy = pk2(V1x, V1y), V2xy = pk2(V2x, V2y);
    u64 N0xy = pk2(N0x, N0y), N1xy = pk2(N1x, N1y), N2xy = pk2(N2x, N2y);
    u64 ntgxy = pk2(-tgx, -tgy);
    u64 SS    = pk2(SSCALE, SSCALE);
    u64 KK    = pk2(K, K);
    u64 B1B1  = pk2(B1, B1),  OB1OB1 = pk2(OB1, OB1);
    u64 B2B2  = pk2(B2, B2),  OB2OB2 = pk2(OB2, OB2);
    u64 nLR2  = pk2(-LR, -LR);
    u64 NEG1  = pk2(-1.0f, -1.0f);
    u64 ZERO2 = pk2(0.0f, 0.0f);

    u64 vwuv = pk2(1.0f/3.0f, 1.0f/3.0f);

#pragma unroll 1
    for (int outer = 0; outer < 4; ++outer) {
        float vwu, vwv; upk2(vwuv, vwu, vwv);
        float w0 = 1.0f - vwu - vwv;
        float Px0 = fmaf(vwu, V0x, fmaf(vwv, V1x, w0 * V2x));
        float Py0 = fmaf(vwu, V0y, fmaf(vwv, V1y, w0 * V2y));
        float Pz0 = fmaf(vwu, V0z, fmaf(vwv, V1z, w0 * V2z));
        float ex = Px0 - qx, ey = Py0 - qy, ez = Pz0 - qz;
        float dd = sqrtf(ex*ex + ey*ey + ez*ez);

        u64 duv = ZERO2, m_uv = ZERO2, v_uv = ZERO2;
        float md = 0.0f, vd = 0.0f;
        float b1t = 1.0f, b2t = 1.0f;

#pragma unroll 1
        for (int t = 0; t < 50; ++t) {
            b1t *= B1; b2t *= B2;
            float ic1 = __fdividef(1.0f, 1.0f - b1t);
            float ic2 = __fdividef(1.0f, 1.0f - b2t);

            u64 uv = add2(vwuv, duv);           // u = vwu + du ; v = vwv + dv
            float u, v; upk2(uv, u, v);
            float w = 1.0f - u - v;

            u64 uu = pk2(u, u), vv = pk2(v, v), ww = pk2(w, w);
            u64 PxPy = fma2(uu, V0xy, fma2(vv, V1xy, mul2(ww, V2xy)));
            u64 NxNy = fma2(uu, N0xy, fma2(vv, N1xy, mul2(ww, N2xy)));
            float Pz = fmaf(u, V0z, fmaf(v, V1z, w * V2z));
            float Nz = fmaf(u, N0z, fmaf(v, N1z, w * N2z));

            float Nx, Ny; upk2(NxNy, Nx, Ny);
            float nn = fmaf(Nx, Nx, fmaf(Ny, Ny, Nz * Nz));
            float l  = sqrtf(nn);
            float rl = __fdividef(1.0f, fmaxf(l, 1e-12f));
            u64 nxny = mul2(NxNy, pk2(rl, rl)); // nx = Nx*rl ; ny = Ny*rl
            float nz = Nz * rl;

            float sd = SSCALE * dd;
            u64 rxry = fma2(SS, PxPy, fma2(pk2(sd, sd), nxny, ntgxy));
            float rz = fmaf(SSCALE, Pz, fmaf(sd, nz, -tgz));

            float rx, ry; upk2(rxry, rx, ry);
            float nx, ny; upk2(nxny, nx, ny);
            float rn = fmaf(rx, nx, fmaf(ry, ny, rz * nz));

            u64 rxrx = pk2(rx, rx), ryry = pk2(ry, ry), rzrz = pk2(rz, rz);
            u64 rvuv = fma2(rxrx, dVuv_x, fma2(ryry, dVuv_y, mul2(rzrz, dVuv_z)));
            u64 rnuv = fma2(rxrx, dNuv_x, fma2(ryry, dNuv_y, mul2(rzrz, dNuv_z)));
            u64 nxnx = pk2(nx, nx), nyny = pk2(ny, ny), nznz = pk2(nz, nz);
            u64 nduv = fma2(nxnx, dNuv_x, fma2(nyny, dNuv_y, mul2(nznz, dNuv_z)));

            float drl = dd * rl;
            u64 nnduv = mul2(nduv, NEG1);       // exact sign flip: (-ndu, -ndv)
            u64 guv = mul2(KK, fma2(pk2(drl, drl), fma2(nnduv, pk2(rn, rn), rnuv), rvuv));
            float gd = K * rn;

            // Adam u,v (packed); identical per-lane value sequences
            m_uv = fma2(B1B1, m_uv, mul2(OB1OB1, guv));
            v_uv = fma2(B2B2, v_uv, mul2(mul2(OB2OB2, guv), guv));   // (OB2*g)*g
            float mu, mv; upk2(m_uv, mu, mv);
            float vu, vvs; upk2(v_uv, vu, vvs);
            float qu = __fdividef(mu * ic1, sqrtf(vu * ic2) + EPSA);
            float qv = __fdividef(mv * ic1, sqrtf(vvs * ic2) + EPSA);
            duv = fma2(nLR2, pk2(qu, qv), duv);  // du = fmaf(-LR, qu, du)

            // Adam d (scalar, unchanged)
            md = fmaf(B1, md, OB1 * gd);
            vd = fmaf(B2, vd, OB2 * gd * gd);
            dd = fmaf(-LR, __fdividef(md * ic1, sqrtf(vd * ic2) + EPSA), dd);
        }
        vwuv = add2(vwuv, duv);                  // vwu += du ; vwv += dv
    }

    // Outputs, flattened tuple as float32: fidx | vw | outlier_mask
    float vwu_o, vwv_o; upk2(vwuv, vwu_o, vwv_o);
    out[i] = (float)fid;
    out[NPTSALL + 2*i + 0] = vwu_o;
    out[NPTSALL + 2*i + 1] = vwv_o;
    out[3*NPTSALL + i] = 0.0f;
}

extern "C" void kernel_launch(void* const* d_in, const int* in_sizes, int n_in,
                              void* d_out, int out_size) {
    const float* verts  = (const float*)d_in[0];
    const float* mesh_V = (const float*)d_in[1];
    const float* mesh_N = (const float*)d_in[2];
    const int*   mesh_F = (const int*)d_in[3];
    float* out = (float*)d_out;

    pack_centers_kernel<<<(NFACES + 127) / 128, 128>>>(mesh_V, mesh_F);
    dim3 gridA(NPTSALL / 256, NOCT);
    knnA_kernel<<<gridA, 128>>>(verts);
    solve_kernel<<<NPTSALL / 128, 128>>>(verts, mesh_V, mesh_N, mesh_F, out);
}

// round 11
// speedup vs baseline: 1.3558x; 1.0442x over previous
#include <cuda_runtime.h>
#include <cstdint>

typedef unsigned long long u64;

#define NPTSALL    16384     // BATCH * N_PTS
#define NFACES     10000
#define NPAIRS     5000      // NFACES / 2
#define NSLC       20
#define SLC_PAIRS  250       // NPAIRS / NSLC
#define NSUB       10
#define SUB_PAIRS  25        // SLC_PAIRS / NSUB
#define SSCALE     10.0f

// Scratch (static __device__ arrays; no allocation)
__device__ float4 d_A[NPAIRS];             // (cx0, cx1, cy0, cy1) per center pair
__device__ float4 d_B[NPAIRS];             // (cz0, cz1, c2_0, c2_1) per center pair
__device__ float  d_qval[NSLC * NPTSALL];  // per-slice min score per point
__device__ int    d_qsub[NSLC * NPTSALL];  // winning subtile base pair index

// ---------------- packed fp32x2 helpers ----------------
__device__ __forceinline__ u64 fma2(u64 a, u64 b, u64 c) {
    u64 d;
    asm("fma.rn.f32x2 %0, %1, %2, %3;" : "=l"(d) : "l"(a), "l"(b), "l"(c));
    return d;
}
__device__ __forceinline__ u64 pk2(float lo, float hi) {
    u64 v; asm("mov.b64 %0, {%1, %2};" : "=l"(v) : "f"(lo), "f"(hi)); return v;
}
__device__ __forceinline__ void upk2(u64 v, float& lo, float& hi) {
    asm("mov.b64 {%0, %1}, %2;" : "=f"(lo), "=f"(hi) : "l"(v));
}

// ---------------- 1) centers + |c|^2 (one thread per face) ----------------
__global__ void pack_centers_kernel(const float* __restrict__ V, const int* __restrict__ F) {
    int f = blockIdx.x * blockDim.x + threadIdx.x;
    if (f >= NFACES) return;
    int i0 = F[3*f+0], i1 = F[3*f+1], i2 = F[3*f+2];
    float x = (V[3*i0+0] + V[3*i1+0] + V[3*i2+0]) / 3.0f;
    float y = (V[3*i0+1] + V[3*i1+1] + V[3*i2+1]) / 3.0f;
    float z = (V[3*i0+2] + V[3*i1+2] + V[3*i2+2]) / 3.0f;
    float c2 = x*x + y*y + z*z;
    int p = f >> 1, h = f & 1;
    float* A = (float*)d_A;
    float* B = (float*)d_B;
    A[4*p + h]     = x;
    A[4*p + 2 + h] = y;
    B[4*p + h]     = z;
    B[4*p + 2 + h] = c2;
}

// ---------------- 2a) per-slice min scan, 2 points per thread ----------------
// score_f = |c_f|^2 - 2 q.c_f (|q|^2 dropped: argmin-invariant); exact same fma2
// chain as all passing rounds. grid (64, 20) = 1280 blocks -> fine-grained wave
// balance (worst SM 9 blocks vs mean 8.65, was 4 vs 3.46). Min VALUE per 25-pair
// subtile; strict < ascending => first-index ties.
__global__ void __launch_bounds__(128) knnA_kernel(const float* __restrict__ verts) {
    __shared__ ulonglong2 sA[SLC_PAIRS];   // 4 KB
    __shared__ ulonglong2 sB[SLC_PAIRS];   // 4 KB
    int tid = threadIdx.x;
    int slc = blockIdx.y;
    int obase = slc * SLC_PAIRS;

    const ulonglong2* gA = (const ulonglong2*)d_A;
    const ulonglong2* gB = (const ulonglong2*)d_B;
    for (int i = tid; i < SLC_PAIRS; i += 128) { sA[i] = gA[obase + i]; sB[i] = gB[obase + i]; }
    __syncthreads();

    int ptA = blockIdx.x * 256 + tid;
    int ptB = ptA + 128;
    float qxA = verts[3*ptA+0], qyA = verts[3*ptA+1], qzA = verts[3*ptA+2];
    float qxB = verts[3*ptB+0], qyB = verts[3*ptB+1], qzB = verts[3*ptB+2];
    u64 qmxA = pk2(-2.0f*qxA, -2.0f*qxA);
    u64 qmyA = pk2(-2.0f*qyA, -2.0f*qyA);
    u64 qmzA = pk2(-2.0f*qzA, -2.0f*qzA);
    u64 qmxB = pk2(-2.0f*qxB, -2.0f*qxB);
    u64 qmyB = pk2(-2.0f*qyB, -2.0f*qyB);
    u64 qmzB = pk2(-2.0f*qzB, -2.0f*qzB);

    const float INF = __int_as_float(0x7f800000);
    float bestA = INF, bestB = INF;
    int subA = 0, subB = 0;

#pragma unroll 1
    for (int s = 0; s < NSUB; ++s) {
        int b = s * SUB_PAIRS;
        float a0 = INF, a1 = INF, b0 = INF, b1 = INF;
#pragma unroll 5
        for (int p = 0; p < SUB_PAIRS; ++p) {
            ulonglong2 A = sA[b + p];
            ulonglong2 B = sB[b + p];
            u64 zA = fma2(B.x, qmzA, B.y);
            u64 zB = fma2(B.x, qmzB, B.y);
            u64 scA = fma2(A.x, qmxA, fma2(A.y, qmyA, zA));
            u64 scB = fma2(A.x, qmxB, fma2(A.y, qmyB, zB));
            float lA, hA, lB, hB;
            upk2(scA, lA, hA); upk2(scB, lB, hB);
            a0 = fminf(a0, lA); a1 = fminf(a1, hA);
            b0 = fminf(b0, lB); b1 = fminf(b1, hB);
        }
        float smA = fminf(a0, a1);
        float smB = fminf(b0, b1);
        if (smA < bestA) { bestA = smA; subA = b; }   // strict <: earliest subtile wins
        if (smB < bestB) { bestB = smB; subB = b; }
    }
    d_qval[slc * NPTSALL + ptA] = bestA;
    d_qsub[slc * NPTSALL + ptA] = obase + subA;
    d_qval[slc * NPTSALL + ptB] = bestB;
    d_qsub[slc * NPTSALL + ptB] = obase + subB;
}

// ---------------- 2b + 3) combine/rescan + 4 x 50 Adam solve ----------------
// R8 form VERBATIM (validated at rel_err 8.026817e-4 three times); only the
// combine loop count changed 8 -> 20 (strict <, ascending => first-index ties).
__global__ void __launch_bounds__(128) solve_kernel(
    const float* __restrict__ verts,
    const float* __restrict__ MV,
    const float* __restrict__ MN,
    const int*   __restrict__ MF,
    float* __restrict__ out)
{
    int i = blockIdx.x * 128 + threadIdx.x;

    float qx = verts[3*i+0], qy = verts[3*i+1], qz = verts[3*i+2];

    // ---- combine slice mins (strict <, ascending => first-index ties) ----
    float best = d_qval[i]; int qi = 0;
#pragma unroll
    for (int q = 1; q < NSLC; ++q) {
        float v = d_qval[q * NPTSALL + i];
        if (v < best) { best = v; qi = q; }
    }
    int base = d_qsub[qi * NPTSALL + i];

    // ---- rescan winning 25-pair subtile, first bitwise-equal index ----
    u64 qmx = pk2(-2.0f*qx, -2.0f*qx);
    u64 qmy = pk2(-2.0f*qy, -2.0f*qy);
    u64 qmz = pk2(-2.0f*qz, -2.0f*qz);
    const ulonglong2* gA = (const ulonglong2*)d_A;
    const ulonglong2* gB = (const ulonglong2*)d_B;
    int found = 0x7fffffff;
#pragma unroll 5
    for (int j = 0; j < SUB_PAIRS; ++j) {
        ulonglong2 a = gA[base + j];
        ulonglong2 b = gB[base + j];
        u64 sc = fma2(a.x, qmx, fma2(a.y, qmy, fma2(b.x, qmz, b.y)));
        float lo, hi; upk2(sc, lo, hi);
        if (lo == best) found = min(found, 2*(base + j));
        if (hi == best) found = min(found, 2*(base + j) + 1);
    }
    int fid = (found == 0x7fffffff) ? 0 : found;   // guaranteed found; OOB guard

    // ---- Adam solve (numerics identical to R2/R4/R8) ----
    int i0 = MF[3*fid+0], i1 = MF[3*fid+1], i2 = MF[3*fid+2];

    float V0x = MV[3*i0+0], V0y = MV[3*i0+1], V0z = MV[3*i0+2];
    float V1x = MV[3*i1+0], V1y = MV[3*i1+1], V1z = MV[3*i1+2];
    float V2x = MV[3*i2+0], V2y = MV[3*i2+1], V2z = MV[3*i2+2];
    float N0x = MN[3*i0+0], N0y = MN[3*i0+1], N0z = MN[3*i0+2];
    float N1x = MN[3*i1+0], N1y = MN[3*i1+1], N1z = MN[3*i1+2];
    float N2x = MN[3*i2+0], N2y = MN[3*i2+1], N2z = MN[3*i2+2];

    float tgx = SSCALE*qx, tgy = SSCALE*qy, tgz = SSCALE*qz;

    float dVux = V0x - V2x, dVuy = V0y - V2y, dVuz = V0z - V2z;
    float dVvx = V1x - V2x, dVvy = V1y - V2y, dVvz = V1z - V2z;
    float dNux = N0x - N2x, dNuy = N0y - N2y, dNuz = N0z - N2z;
    float dNvx = N1x - N2x, dNvy = N1y - N2y, dNvz = N1z - N2z;

    const float B1 = 0.9f, B2 = 0.999f, LR = 0.01f, EPSA = 1e-8f;
    const float OB1 = 1.0f - 0.9f;
    const float OB2 = 1.0f - 0.999f;
    const float K   = (2.0f / 49152.0f) * SSCALE;  // 2/(3M) * S

    float vwu = 1.0f/3.0f, vwv = 1.0f/3.0f;

#pragma unroll 1
    for (int outer = 0; outer < 4; ++outer) {
        float w0 = 1.0f - vwu - vwv;
        float Px0 = fmaf(vwu, V0x, fmaf(vwv, V1x, w0 * V2x));
        float Py0 = fmaf(vwu, V0y, fmaf(vwv, V1y, w0 * V2y));
        float Pz0 = fmaf(vwu, V0z, fmaf(vwv, V1z, w0 * V2z));
        float ex = Px0 - qx, ey = Py0 - qy, ez = Pz0 - qz;
        float dd = sqrtf(ex*ex + ey*ey + ez*ez);

        float du = 0.0f, dv = 0.0f;
        float mu = 0.0f, mv = 0.0f, md = 0.0f;
        float vu = 0.0f, vvv = 0.0f, vd = 0.0f;
        float b1t = 1.0f, b2t = 1.0f;

#pragma unroll 1
        for (int t = 0; t < 50; ++t) {
            b1t *= B1; b2t *= B2;
            float u = vwu + du, v = vwv + dv;
            float w = 1.0f - u - v;

            float Px = fmaf(u, V0x, fmaf(v, V1x, w * V2x));
            float Py = fmaf(u, V0y, fmaf(v, V1y, w * V2y));
            float Pz = fmaf(u, V0z, fmaf(v, V1z, w * V2z));
            float Nx = fmaf(u, N0x, fmaf(v, N1x, w * N2x));
            float Ny = fmaf(u, N0y, fmaf(v, N1y, w * N2y));
            float Nz = fmaf(u, N0z, fmaf(v, N1z, w * N2z));

            float nn = fmaf(Nx, Nx, fmaf(Ny, Ny, Nz * Nz));
            float l  = sqrtf(nn);
            float rl = __fdividef(1.0f, fmaxf(l, 1e-12f));
            float nx = Nx * rl, ny = Ny * rl, nz = Nz * rl;

            float sd = SSCALE * dd;
            float rx = fmaf(SSCALE, Px, fmaf(sd, nx, -tgx));
            float ry = fmaf(SSCALE, Py, fmaf(sd, ny, -tgy));
            float rz = fmaf(SSCALE, Pz, fmaf(sd, nz, -tgz));

            float rn  = fmaf(rx, nx,   fmaf(ry, ny,   rz * nz));
            float rvu = fmaf(rx, dVux, fmaf(ry, dVuy, rz * dVuz));
            float rvv = fmaf(rx, dVvx, fmaf(ry, dVvy, rz * dVvz));
            float rnu = fmaf(rx, dNux, fmaf(ry, dNuy, rz * dNuz));
            float rnv = fmaf(rx, dNvx, fmaf(ry, dNvy, rz * dNvz));
            float ndu = fmaf(nx, dNux, fmaf(ny, dNuy, nz * dNuz));
            float ndv = fmaf(nx, dNvx, fmaf(ny, dNvy, nz * dNvz));

            float drl = dd * rl;
            float gu = K * fmaf(drl, fmaf(-ndu, rn, rnu), rvu);
            float gv = K * fmaf(drl, fmaf(-ndv, rn, rnv), rvv);
            float gd = K * rn;

            float ic1 = __fdividef(1.0f, 1.0f - b1t);
            float ic2 = __fdividef(1.0f, 1.0f - b2t);

            mu = fmaf(B1, mu, OB1 * gu);
            vu = fmaf(B2, vu, OB2 * gu * gu);
            du = fmaf(-LR, __fdividef(mu * ic1, sqrtf(vu * ic2) + EPSA), du);

            mv = fmaf(B1, mv, OB1 * gv);
            vvv = fmaf(B2, vvv, OB2 * gv * gv);
            dv = fmaf(-LR, __fdividef(mv * ic1, sqrtf(vvv * ic2) + EPSA), dv);

            md = fmaf(B1, md, OB1 * gd);
            vd = fmaf(B2, vd, OB2 * gd * gd);
            dd = fmaf(-LR, __fdividef(md * ic1, sqrtf(vd * ic2) + EPSA), dd);
        }
        vwu += du; vwv += dv;
    }

    // Outputs, flattened tuple as float32: fidx | vw | outlier_mask
    out[i] = (float)fid;
    out[NPTSALL + 2*i + 0] = vwu;
    out[NPTSALL + 2*i + 1] = vwv;
    out[3*NPTSALL + i] = 0.0f;
}

extern "C" void kernel_launch(void* const* d_in, const int* in_sizes, int n_in,
                              void* d_out, int out_size) {
    const float* verts  = (const float*)d_in[0];
    const float* mesh_V = (const float*)d_in[1];
    const float* mesh_N = (const float*)d_in[2];
    const int*   mesh_F = (const int*)d_in[3];
    float* out = (float*)d_out;

    pack_centers_kernel<<<(NFACES + 127) / 128, 128>>>(mesh_V, mesh_F);
    dim3 gridA(NPTSALL / 256, NSLC);
    knnA_kernel<<<gridA, 128>>>(verts);
    solve_kernel<<<NPTSALL / 128, 128>>>(verts, mesh_V, mesh_N, mesh_F, out);
}